// round 10
// baseline (speedup 1.0000x reference)
#include <cuda_runtime.h>
#include <cuda_bf16.h>
#include <stdint.h>
#include <math.h>

#define HEADS 12
#define HEAD_SIZE 64
#define HIDDEN 768
#define EPROJ 1536
#define SEQ 1024
#define NB 8
#define NEGV 1000000000000.0f

// bf16 staging buffers
__device__ __align__(128) __nv_bfloat16 g_xb[NB * SEQ * HIDDEN];   // [8192][768]
__device__ __align__(128) __nv_bfloat16 g_wt[EPROJ * HIDDEN];      // W^T, rows permuted
__device__ __align__(128) __nv_bfloat16 g_q[NB * HEADS * SEQ * HEAD_SIZE];
__device__ __align__(128) __nv_bfloat16 g_k[NB * HEADS * SEQ * HEAD_SIZE]; // rows permuted

#define SWZ(o) ((o) ^ (((o) >> 3) & 0x70))

// Involutive permutation within 32-row groups: c = (a<<3)|(b<<1)|q -> (b<<3)|(a<<1)|q.
// With B/K rows stored permuted, mma fragment col c maps to global col
// (lane&3)*8 + ni*2 + q, i.e. each lane owns 8 contiguous output columns.
__device__ __forceinline__ int permg(int c) {
    return (((c & 7) >> 1) << 3) + ((c >> 3) << 1) + (c & 1);
}

__device__ __forceinline__ uint32_t smem_u32(const void* p) {
    uint32_t a;
    asm("{ .reg .u64 t; cvta.to.shared.u64 t, %1; cvt.u32.u64 %0, t; }"
        : "=r"(a) : "l"(p));
    return a;
}

__device__ __forceinline__ void ldmx4(uint32_t* r, uint32_t addr) {
    asm volatile("ldmatrix.sync.aligned.m8n8.x4.shared.b16 {%0,%1,%2,%3}, [%4];"
                 : "=r"(r[0]), "=r"(r[1]), "=r"(r[2]), "=r"(r[3]) : "r"(addr));
}
__device__ __forceinline__ void ldmx2(uint32_t* r, uint32_t addr) {
    asm volatile("ldmatrix.sync.aligned.m8n8.x2.shared.b16 {%0,%1}, [%2];"
                 : "=r"(r[0]), "=r"(r[1]) : "r"(addr));
}
__device__ __forceinline__ void mma16816(float* c, const uint32_t* a,
                                         const uint32_t* b) {
    asm volatile(
        "mma.sync.aligned.m16n8k16.row.col.f32.bf16.bf16.f32 "
        "{%0,%1,%2,%3}, {%4,%5,%6,%7}, {%8,%9}, {%0,%1,%2,%3};"
        : "+f"(c[0]), "+f"(c[1]), "+f"(c[2]), "+f"(c[3])
        : "r"(a[0]), "r"(a[1]), "r"(a[2]), "r"(a[3]), "r"(b[0]), "r"(b[1]));
}

// ---------------------------------------------------------------------------
// conversion kernels
// ---------------------------------------------------------------------------
__global__ void conv_x_kernel(const float* __restrict__ x) {
    int i = blockIdx.x * blockDim.x + threadIdx.x;  // float4 index
    float4 v = ((const float4*)x)[i];
    __nv_bfloat162 lo, hi;
    lo.x = __float2bfloat16(v.x); lo.y = __float2bfloat16(v.y);
    hi.x = __float2bfloat16(v.z); hi.y = __float2bfloat16(v.w);
    uint2 u;
    u.x = *(uint32_t*)&lo; u.y = *(uint32_t*)&hi;
    ((uint2*)g_xb)[i] = u;
}

// W^T with permuted rows (within aligned 32-row groups).
__global__ void conv_wt_kernel(const float* __restrict__ W) {
    __shared__ float t[32][33];
    int bx = blockIdx.x * 32, by = blockIdx.y * 32;
#pragma unroll
    for (int j = 0; j < 4; j++)
        t[threadIdx.y + j * 8][threadIdx.x] =
            W[(size_t)(by + threadIdx.y + j * 8) * EPROJ + bx + threadIdx.x];
    __syncthreads();
#pragma unroll
    for (int j = 0; j < 4; j++) {
        const int lr = threadIdx.y + j * 8;          // 0..31 within group
        g_wt[(size_t)(bx + permg(lr)) * HIDDEN + by + threadIdx.x] =
            __float2bfloat16(t[threadIdx.x][lr]);
    }
}

// ---------------------------------------------------------------------------
// Kernel 1: proj = x @ W (+bias) then RoPE -> g_q / g_k (bf16)
// CTA tile 128x128, K in chunks of 64. 8 warps: 2(m) x 4(n), warp tile 64x32.
// g_wt is pre-permuted -> linear coalesced loads + contiguous-col epilogue.
// g_k is written permuted (for the logits kernel); g_q linear.
// ---------------------------------------------------------------------------
__global__ void __launch_bounds__(256, 2) proj_kernel(const float* __restrict__ bias) {
    __shared__ __align__(128) __nv_bfloat16 sA[128 * 64];  // [m][k] 128B rows
    __shared__ __align__(128) __nv_bfloat16 sB[128 * 64];  // [n][k] (permuted rows)
    __shared__ float s_inv[32];
    __shared__ float s_bias[128];

    const int tid = threadIdx.x;
    const int lane = tid & 31;
    const int wid = tid >> 5;
    const int wm = wid & 1;   // 0..1
    const int wn = wid >> 1;  // 0..3
    const int h = blockIdx.x;             // head tile (12)
    const int rowBase = blockIdx.y * 128; // token rows
    const int colBase = h * 128;

    if (tid < 32) s_inv[tid] = exp2f(-(float)(2 * tid) * (13.287712379549449f / 64.0f));
    if (tid < 128) s_bias[tid] = bias[colBase + tid];

    const uint32_t sAb = smem_u32(sA);
    const uint32_t sBb = smem_u32(sB);

    float acc[4][4][4] = {};

    for (int ch = 0; ch < 12; ch++) {
        const int k0 = ch * 64;
        __syncthreads();
#pragma unroll
        for (int i = 0; i < 4; i++) {
            int e = tid + i * 256;   // uint4 index, 1024 per tile
            int r = e >> 3;
            int c = e & 7;
            uint32_t so = SWZ((uint32_t)(r * 128 + c * 16));
            *(uint4*)((char*)sA + so) =
                *(const uint4*)(g_xb + (size_t)(rowBase + r) * HIDDEN + k0 + c * 8);
            *(uint4*)((char*)sB + so) =
                *(const uint4*)(g_wt + (size_t)(colBase + r) * HIDDEN + k0 + c * 8);
        }
        __syncthreads();

#pragma unroll
        for (int ks = 0; ks < 4; ks++) {
            uint32_t aF[4][4], bF[4][2];
#pragma unroll
            for (int mi = 0; mi < 4; mi++) {
                int r = wm * 64 + mi * 16 + (lane & 15);
                int cc = ks * 2 + (lane >> 4);
                ldmx4(aF[mi], sAb + SWZ((uint32_t)(r * 128 + cc * 16)));
            }
#pragma unroll
            for (int ni = 0; ni < 4; ni++) {
                int l = lane & 15;
                int r = wn * 32 + ni * 8 + (l & 7);
                int cc = ks * 2 + (l >> 3);
                ldmx2(bF[ni], sBb + SWZ((uint32_t)(r * 128 + cc * 16)));
            }
#pragma unroll
            for (int mi = 0; mi < 4; mi++)
#pragma unroll
                for (int ni = 0; ni < 4; ni++)
                    mma16816(acc[mi][ni], aF[mi], bF[ni]);
        }
    }

    // Epilogue: lane owns global cols bc..bc+7 (contiguous thanks to the
    // pre-permuted W^T). bias + RoPE, pack 4x bf16x2, one 16B store per
    // (mi, rr). k rows go to permuted slots (consumed linearly by logits).
    const int bc = wn * 32 + (lane & 3) * 8;  // global col base within 128
    const int half = (bc >> 6) & 1;           // 0=q, 1=k
    const int d0 = bc & 63;                   // 8-aligned
    __nv_bfloat16* dstBase = half ? g_k : g_q;
#pragma unroll
    for (int mi = 0; mi < 4; mi++) {
#pragma unroll
        for (int rr = 0; rr < 2; rr++) {
            const int r = rowBase + wm * 64 + mi * 16 + (lane >> 2) + rr * 8;
            const int bb = r >> 10;
            const int n = r & (SEQ - 1);          // true token position (RoPE)
            const int nw = half ? ((n & ~31) | permg(n & 31)) : n;  // storage row
            const float fn = (float)n;
            __nv_bfloat16* drow =
                dstBase + ((size_t)(bb * HEADS + h) * SEQ + nw) * HEAD_SIZE;
            uint32_t pk[4];
#pragma unroll
            for (int j = 0; j < 4; j++) {     // pair j = cols bc+2j, bc+2j+1
                float s, cs;
                sincosf(fn * s_inv[(d0 >> 1) + j], &s, &cs);
                const float v0 = acc[mi][j][rr * 2 + 0] + s_bias[bc + 2 * j];
                const float v1 = acc[mi][j][rr * 2 + 1] + s_bias[bc + 2 * j + 1];
                __nv_bfloat162 o;
                o.x = __float2bfloat16(v0 * cs - v1 * s);
                o.y = __float2bfloat16(v1 * cs + v0 * s);
                pk[j] = *(uint32_t*)&o;
            }
            uint4 u;
            u.x = pk[0]; u.y = pk[1]; u.z = pk[2]; u.w = pk[3];
            *(uint4*)(drow + d0) = u;
        }
    }
}

// ---------------------------------------------------------------------------
// Kernel 2: logits tile 128x128 per CTA: D = q @ k^T, mask/causal/scale.
// Causal skip: tiles strictly below the diagonal (m0 >= n0+128) are fully
// dominated by the -NEG tril term; their O(1) acc contribution is ~8e-12
// elementwise-relative, so the GEMM (loads + mma) is skipped and the
// unchanged epilogue runs with acc = 0.
// ---------------------------------------------------------------------------
__global__ void __launch_bounds__(256, 2) logits_kernel(const float* __restrict__ mask,
                                                        float* __restrict__ out) {
    __shared__ __align__(128) __nv_bfloat16 sQ[128 * 64];
    __shared__ __align__(128) __nv_bfloat16 sK[128 * 64];
    __shared__ float s_mk[128];

    const int tid = threadIdx.x;
    const int lane = tid & 31;
    const int wid = tid >> 5;
    const int wm = wid & 1;
    const int wn = wid >> 1;
    const int z = blockIdx.z;
    const int b = z / HEADS;
    const int m0 = blockIdx.y << 7;
    const int n0 = blockIdx.x << 7;

    if (tid < 128) s_mk[tid] = mask[(size_t)b * SEQ + n0 + tid];

    float acc[4][4][4] = {};

    const bool skip = (blockIdx.y > blockIdx.x);   // strictly below diagonal
    if (!skip) {
        const __nv_bfloat16* qsrc = g_q + ((size_t)z * SEQ + m0) * HEAD_SIZE;
        const __nv_bfloat16* ksrc = g_k + ((size_t)z * SEQ + n0) * HEAD_SIZE;

#pragma unroll
        for (int i = 0; i < 4; i++) {
            int e = tid + i * 256;
            uint32_t so = SWZ((uint32_t)(e * 16));
            *(uint4*)((char*)sQ + so) = ((const uint4*)qsrc)[e];
            *(uint4*)((char*)sK + so) = ((const uint4*)ksrc)[e];
        }
        __syncthreads();

        const uint32_t sQb = smem_u32(sQ);
        const uint32_t sKb = smem_u32(sK);

#pragma unroll
        for (int ks = 0; ks < 4; ks++) {
            uint32_t aF[4][4], bF[4][2];
#pragma unroll
            for (int mi = 0; mi < 4; mi++) {
                int r = wm * 64 + mi * 16 + (lane & 15);
                int cc = ks * 2 + (lane >> 4);
                ldmx4(aF[mi], sQb + SWZ((uint32_t)(r * 128 + cc * 16)));
            }
#pragma unroll
            for (int ni = 0; ni < 4; ni++) {
                int l = lane & 15;
                int r = wn * 32 + ni * 8 + (l & 7);
                int cc = ks * 2 + (l >> 3);
                ldmx2(bF[ni], sKb + SWZ((uint32_t)(r * 128 + cc * 16)));
            }
#pragma unroll
            for (int mi = 0; mi < 4; mi++)
#pragma unroll
                for (int ni = 0; ni < 4; ni++)
                    mma16816(acc[mi][ni], aF[mi], bF[ni]);
        }
    } else {
        __syncthreads();   // keep barrier count uniform (s_mk visibility)
    }

    // Epilogue: lane owns global cols bc..bc+7; mask/causal/scale; 2x STG.128.
    const int bc = wn * 32 + (lane & 3) * 8;   // col base within 128
#pragma unroll
    for (int mi = 0; mi < 4; mi++) {
#pragma unroll
        for (int rr = 0; rr < 2; rr++) {
            const int m = m0 + wm * 64 + mi * 16 + (lane >> 2) + rr * 8;
            const float mq = mask[(size_t)b * SEQ + m];
            const float rbias = NEGV * (mq - 1.0f);
            float* orow = out + ((size_t)z * SEQ + m) * SEQ + n0;
            float v[8];
#pragma unroll
            for (int j = 0; j < 4; j++) {
#pragma unroll
                for (int q = 0; q < 2; q++) {
                    const int jj = 2 * j + q;          // 0..7 within lane
                    const int col = bc + jj;
                    const int nn = n0 + col;
                    const float mk = s_mk[col];
                    float t = acc[mi][j][rr * 2 + q];
                    t = t * mq + rbias;
                    t = t * mk + NEGV * (mk - 1.0f);
                    if (m > nn) t -= NEGV;
                    v[jj] = t * 0.125f;
                }
            }
            float4 o0, o1;
            o0.x = v[0]; o0.y = v[1]; o0.z = v[2]; o0.w = v[3];
            o1.x = v[4]; o1.y = v[5]; o1.z = v[6]; o1.w = v[7];
            *(float4*)(orow + bc) = o0;
            *(float4*)(orow + bc + 4) = o1;
        }
    }
}

// ---------------------------------------------------------------------------
extern "C" void kernel_launch(void* const* d_in, const int* in_sizes, int n_in,
                              void* d_out, int out_size) {
    const float* x = (const float*)d_in[0];
    const float* W = (const float*)d_in[1];
    const float* bias = (const float*)d_in[2];
    const float* mask = (const float*)d_in[3];
    float* out = (float*)d_out;

    conv_x_kernel<<<(NB * SEQ * HIDDEN / 4) / 256, 256>>>(x);
    conv_wt_kernel<<<dim3(EPROJ / 32, HIDDEN / 32), dim3(32, 8)>>>(W);

    proj_kernel<<<dim3(EPROJ / 128, NB * SEQ / 128), 256>>>(bias);

    logits_kernel<<<dim3(SEQ / 128, SEQ / 128, NB * HEADS), 256>>>(mask, out);
}

// round 11
// speedup vs baseline: 1.0256x; 1.0256x over previous
#include <cuda_runtime.h>
#include <cuda_bf16.h>
#include <stdint.h>
#include <math.h>

#define HEADS 12
#define HEAD_SIZE 64
#define HIDDEN 768
#define EPROJ 1536
#define SEQ 1024
#define NB 8
#define NEGV 1000000000000.0f

// bf16 staging buffers
__device__ __align__(128) __nv_bfloat16 g_xb[NB * SEQ * HIDDEN];   // [8192][768]
__device__ __align__(128) __nv_bfloat16 g_wt[EPROJ * HIDDEN];      // W^T, rows permuted
__device__ __align__(128) __nv_bfloat16 g_q[NB * HEADS * SEQ * HEAD_SIZE];
__device__ __align__(128) __nv_bfloat16 g_k[NB * HEADS * SEQ * HEAD_SIZE]; // rows permuted

#define SWZ(o) ((o) ^ (((o) >> 3) & 0x70))

// Involutive permutation within 32-row groups: c = (a<<3)|(b<<1)|q -> (b<<3)|(a<<1)|q.
// With B/K rows stored permuted, mma fragment col c maps to global col
// (lane&3)*8 + ni*2 + q, i.e. each lane owns 8 contiguous output columns.
__device__ __forceinline__ int permg(int c) {
    return (((c & 7) >> 1) << 3) + ((c >> 3) << 1) + (c & 1);
}

__device__ __forceinline__ uint32_t smem_u32(const void* p) {
    uint32_t a;
    asm("{ .reg .u64 t; cvta.to.shared.u64 t, %1; cvt.u32.u64 %0, t; }"
        : "=r"(a) : "l"(p));
    return a;
}

__device__ __forceinline__ void ldmx4(uint32_t* r, uint32_t addr) {
    asm volatile("ldmatrix.sync.aligned.m8n8.x4.shared.b16 {%0,%1,%2,%3}, [%4];"
                 : "=r"(r[0]), "=r"(r[1]), "=r"(r[2]), "=r"(r[3]) : "r"(addr));
}
__device__ __forceinline__ void ldmx2(uint32_t* r, uint32_t addr) {
    asm volatile("ldmatrix.sync.aligned.m8n8.x2.shared.b16 {%0,%1}, [%2];"
                 : "=r"(r[0]), "=r"(r[1]) : "r"(addr));
}
__device__ __forceinline__ void mma16816(float* c, const uint32_t* a,
                                         const uint32_t* b) {
    asm volatile(
        "mma.sync.aligned.m16n8k16.row.col.f32.bf16.bf16.f32 "
        "{%0,%1,%2,%3}, {%4,%5,%6,%7}, {%8,%9}, {%0,%1,%2,%3};"
        : "+f"(c[0]), "+f"(c[1]), "+f"(c[2]), "+f"(c[3])
        : "r"(a[0]), "r"(a[1]), "r"(a[2]), "r"(a[3]), "r"(b[0]), "r"(b[1]));
}

// ---------------------------------------------------------------------------
// conversion kernels
// ---------------------------------------------------------------------------
__global__ void conv_x_kernel(const float* __restrict__ x) {
    int i = blockIdx.x * blockDim.x + threadIdx.x;  // float4 index
    float4 v = ((const float4*)x)[i];
    __nv_bfloat162 lo, hi;
    lo.x = __float2bfloat16(v.x); lo.y = __float2bfloat16(v.y);
    hi.x = __float2bfloat16(v.z); hi.y = __float2bfloat16(v.w);
    uint2 u;
    u.x = *(uint32_t*)&lo; u.y = *(uint32_t*)&hi;
    ((uint2*)g_xb)[i] = u;
}

// W^T with permuted rows (within aligned 32-row groups).
__global__ void conv_wt_kernel(const float* __restrict__ W) {
    __shared__ float t[32][33];
    int bx = blockIdx.x * 32, by = blockIdx.y * 32;
#pragma unroll
    for (int j = 0; j < 4; j++)
        t[threadIdx.y + j * 8][threadIdx.x] =
            W[(size_t)(by + threadIdx.y + j * 8) * EPROJ + bx + threadIdx.x];
    __syncthreads();
#pragma unroll
    for (int j = 0; j < 4; j++) {
        const int lr = threadIdx.y + j * 8;          // 0..31 within group
        g_wt[(size_t)(bx + permg(lr)) * HIDDEN + by + threadIdx.x] =
            __float2bfloat16(t[threadIdx.x][lr]);
    }
}

// ---------------------------------------------------------------------------
// Kernel 1: proj = x @ W (+bias) then RoPE -> g_q / g_k (bf16)
// (R9 config: ~94us incl. convs, ~88% of SIMT-HMMA ceiling.)
// ---------------------------------------------------------------------------
__global__ void __launch_bounds__(256, 2) proj_kernel(const float* __restrict__ bias) {
    __shared__ __align__(128) __nv_bfloat16 sA[128 * 64];
    __shared__ __align__(128) __nv_bfloat16 sB[128 * 64];
    __shared__ float s_inv[32];
    __shared__ float s_bias[128];

    const int tid = threadIdx.x;
    const int lane = tid & 31;
    const int wid = tid >> 5;
    const int wm = wid & 1;
    const int wn = wid >> 1;
    const int h = blockIdx.x;
    const int rowBase = blockIdx.y * 128;
    const int colBase = h * 128;

    if (tid < 32) s_inv[tid] = exp2f(-(float)(2 * tid) * (13.287712379549449f / 64.0f));
    if (tid < 128) s_bias[tid] = bias[colBase + tid];

    const uint32_t sAb = smem_u32(sA);
    const uint32_t sBb = smem_u32(sB);

    float acc[4][4][4] = {};

    for (int ch = 0; ch < 12; ch++) {
        const int k0 = ch * 64;
        __syncthreads();
#pragma unroll
        for (int i = 0; i < 4; i++) {
            int e = tid + i * 256;
            int r = e >> 3;
            int c = e & 7;
            uint32_t so = SWZ((uint32_t)(r * 128 + c * 16));
            *(uint4*)((char*)sA + so) =
                *(const uint4*)(g_xb + (size_t)(rowBase + r) * HIDDEN + k0 + c * 8);
            *(uint4*)((char*)sB + so) =
                *(const uint4*)(g_wt + (size_t)(colBase + r) * HIDDEN + k0 + c * 8);
        }
        __syncthreads();

#pragma unroll
        for (int ks = 0; ks < 4; ks++) {
            uint32_t aF[4][4], bF[4][2];
#pragma unroll
            for (int mi = 0; mi < 4; mi++) {
                int r = wm * 64 + mi * 16 + (lane & 15);
                int cc = ks * 2 + (lane >> 4);
                ldmx4(aF[mi], sAb + SWZ((uint32_t)(r * 128 + cc * 16)));
            }
#pragma unroll
            for (int ni = 0; ni < 4; ni++) {
                int l = lane & 15;
                int r = wn * 32 + ni * 8 + (l & 7);
                int cc = ks * 2 + (l >> 3);
                ldmx2(bF[ni], sBb + SWZ((uint32_t)(r * 128 + cc * 16)));
            }
#pragma unroll
            for (int mi = 0; mi < 4; mi++)
#pragma unroll
                for (int ni = 0; ni < 4; ni++)
                    mma16816(acc[mi][ni], aF[mi], bF[ni]);
        }
    }

    const int bc = wn * 32 + (lane & 3) * 8;
    const int half = (bc >> 6) & 1;
    const int d0 = bc & 63;
    __nv_bfloat16* dstBase = half ? g_k : g_q;
#pragma unroll
    for (int mi = 0; mi < 4; mi++) {
#pragma unroll
        for (int rr = 0; rr < 2; rr++) {
            const int r = rowBase + wm * 64 + mi * 16 + (lane >> 2) + rr * 8;
            const int bb = r >> 10;
            const int n = r & (SEQ - 1);
            const int nw = half ? ((n & ~31) | permg(n & 31)) : n;
            const float fn = (float)n;
            __nv_bfloat16* drow =
                dstBase + ((size_t)(bb * HEADS + h) * SEQ + nw) * HEAD_SIZE;
            uint32_t pk[4];
#pragma unroll
            for (int j = 0; j < 4; j++) {
                float s, cs;
                sincosf(fn * s_inv[(d0 >> 1) + j], &s, &cs);
                const float v0 = acc[mi][j][rr * 2 + 0] + s_bias[bc + 2 * j];
                const float v1 = acc[mi][j][rr * 2 + 1] + s_bias[bc + 2 * j + 1];
                __nv_bfloat162 o;
                o.x = __float2bfloat16(v0 * cs - v1 * s);
                o.y = __float2bfloat16(v1 * cs + v0 * s);
                pk[j] = *(uint32_t*)&o;
            }
            uint4 u;
            u.x = pk[0]; u.y = pk[1]; u.z = pk[2]; u.w = pk[3];
            *(uint4*)(drow + d0) = u;
        }
    }
}

// ---------------------------------------------------------------------------
// Kernel 2: logits tile 128(m) x 64(n) per CTA. Smaller tile -> 32 accs/thread
// -> ~80 regs -> 3 CTAs/SM (occ ~33%) to hide STG latency. 8 warps: 4(m)x2(n),
// warp tile 32x32. Causal skip for tiles fully below the diagonal.
// ---------------------------------------------------------------------------
__global__ void __launch_bounds__(256, 3) logits_kernel(const float* __restrict__ mask,
                                                        float* __restrict__ out) {
    __shared__ __align__(128) __nv_bfloat16 sQ[128 * 64];  // 16KB
    __shared__ __align__(128) __nv_bfloat16 sK[64 * 64];   // 8KB
    __shared__ float s_mk[64];

    const int tid = threadIdx.x;
    const int lane = tid & 31;
    const int wid = tid >> 5;
    const int wm = wid & 3;    // 0..3 (m)
    const int wn = wid >> 2;   // 0..1 (n)
    const int z = blockIdx.z;
    const int b = z / HEADS;
    const int m0 = blockIdx.y << 7;
    const int n0 = blockIdx.x << 6;

    if (tid < 64) s_mk[tid] = mask[(size_t)b * SEQ + n0 + tid];

    float acc[2][4][4] = {};

    const bool skip = (m0 >= n0 + 64);   // tile strictly below diagonal
    if (!skip) {
        const __nv_bfloat16* qsrc = g_q + ((size_t)z * SEQ + m0) * HEAD_SIZE;
        const __nv_bfloat16* ksrc = g_k + ((size_t)z * SEQ + n0) * HEAD_SIZE;

#pragma unroll
        for (int i = 0; i < 4; i++) {     // 1024 uint4 for Q
            int e = tid + i * 256;
            uint32_t so = SWZ((uint32_t)(e * 16));
            *(uint4*)((char*)sQ + so) = ((const uint4*)qsrc)[e];
        }
#pragma unroll
        for (int i = 0; i < 2; i++) {     // 512 uint4 for K
            int e = tid + i * 256;
            uint32_t so = SWZ((uint32_t)(e * 16));
            *(uint4*)((char*)sK + so) = ((const uint4*)ksrc)[e];
        }
        __syncthreads();

        const uint32_t sQb = smem_u32(sQ);
        const uint32_t sKb = smem_u32(sK);

#pragma unroll
        for (int ks = 0; ks < 4; ks++) {
            uint32_t aF[2][4], bF[4][2];
#pragma unroll
            for (int mi = 0; mi < 2; mi++) {
                int r = wm * 32 + mi * 16 + (lane & 15);
                int cc = ks * 2 + (lane >> 4);
                ldmx4(aF[mi], sQb + SWZ((uint32_t)(r * 128 + cc * 16)));
            }
#pragma unroll
            for (int ni = 0; ni < 4; ni++) {
                int l = lane & 15;
                int r = wn * 32 + ni * 8 + (l & 7);
                int cc = ks * 2 + (l >> 3);
                ldmx2(bF[ni], sKb + SWZ((uint32_t)(r * 128 + cc * 16)));
            }
#pragma unroll
            for (int mi = 0; mi < 2; mi++)
#pragma unroll
                for (int ni = 0; ni < 4; ni++)
                    mma16816(acc[mi][ni], aF[mi], bF[ni]);
        }
    } else {
        __syncthreads();
    }

    // Epilogue: lane owns cols bc..bc+7. Per-lane col factors (x0.125 folded):
    // v = (acc*mq + rbias)*s_j + o_j  (- 0.125*NEG if causal).
    const int bc = wn * 32 + (lane & 3) * 8;
    float s_j[8], o_j[8];
#pragma unroll
    for (int j = 0; j < 8; j++) {
        const float mk = s_mk[bc + j];
        s_j[j] = mk * 0.125f;
        o_j[j] = (NEGV * 0.125f) * (mk - 1.0f);
    }
#pragma unroll
    for (int mi = 0; mi < 2; mi++) {
#pragma unroll
        for (int rr = 0; rr < 2; rr++) {
            const int m = m0 + wm * 32 + mi * 16 + (lane >> 2) + rr * 8;
            const float mq = mask[(size_t)b * SEQ + m];
            const float rbias = NEGV * (mq - 1.0f);
            float* orow = out + ((size_t)z * SEQ + m) * SEQ + n0;
            float v[8];
#pragma unroll
            for (int j = 0; j < 4; j++) {
#pragma unroll
                for (int q = 0; q < 2; q++) {
                    const int jj = 2 * j + q;
                    const float t = fmaf(acc[mi][j][rr * 2 + q], mq, rbias);
                    float r = fmaf(t, s_j[jj], o_j[jj]);
                    if (m > n0 + bc + jj) r -= (NEGV * 0.125f);
                    v[jj] = r;
                }
            }
            float4 o0, o1;
            o0.x = v[0]; o0.y = v[1]; o0.z = v[2]; o0.w = v[3];
            o1.x = v[4]; o1.y = v[5]; o1.z = v[6]; o1.w = v[7];
            *(float4*)(orow + bc) = o0;
            *(float4*)(orow + bc + 4) = o1;
        }
    }
}

// ---------------------------------------------------------------------------
extern "C" void kernel_launch(void* const* d_in, const int* in_sizes, int n_in,
                              void* d_out, int out_size) {
    const float* x = (const float*)d_in[0];
    const float* W = (const float*)d_in[1];
    const float* bias = (const float*)d_in[2];
    const float* mask = (const float*)d_in[3];
    float* out = (float*)d_out;

    conv_x_kernel<<<(NB * SEQ * HIDDEN / 4) / 256, 256>>>(x);
    conv_wt_kernel<<<dim3(EPROJ / 32, HIDDEN / 32), dim3(32, 8)>>>(W);

    proj_kernel<<<dim3(EPROJ / 128, NB * SEQ / 128), 256>>>(bias);

    logits_kernel<<<dim3(SEQ / 64, SEQ / 128, NB * HEADS), 256>>>(mask, out);
}

// round 12
// speedup vs baseline: 1.1600x; 1.1311x over previous
#include <cuda_runtime.h>
#include <cuda_bf16.h>
#include <stdint.h>
#include <math.h>

#define HEADS 12
#define HEAD_SIZE 64
#define HIDDEN 768
#define EPROJ 1536
#define SEQ 1024
#define NB 8
#define NEGV 1000000000000.0f

// bf16 staging buffers
__device__ __align__(128) __nv_bfloat16 g_xb[NB * SEQ * HIDDEN];   // [8192][768]
__device__ __align__(128) __nv_bfloat16 g_wt[EPROJ * HIDDEN];      // W^T, rows permuted
__device__ __align__(128) __nv_bfloat16 g_q[NB * HEADS * SEQ * HEAD_SIZE];
__device__ __align__(128) __nv_bfloat16 g_k[NB * HEADS * SEQ * HEAD_SIZE]; // rows permuted

#define SWZ(o) ((o) ^ (((o) >> 3) & 0x70))

// Involutive permutation within 32-row groups: c = (a<<3)|(b<<1)|q -> (b<<3)|(a<<1)|q.
// With B/K rows stored permuted, mma fragment col c maps to global col
// (lane&3)*8 + ni*2 + q, i.e. each lane owns 8 contiguous output columns.
__device__ __forceinline__ int permg(int c) {
    return (((c & 7) >> 1) << 3) + ((c >> 3) << 1) + (c & 1);
}

__device__ __forceinline__ uint32_t smem_u32(const void* p) {
    uint32_t a;
    asm("{ .reg .u64 t; cvta.to.shared.u64 t, %1; cvt.u32.u64 %0, t; }"
        : "=r"(a) : "l"(p));
    return a;
}

__device__ __forceinline__ void ldmx4(uint32_t* r, uint32_t addr) {
    asm volatile("ldmatrix.sync.aligned.m8n8.x4.shared.b16 {%0,%1,%2,%3}, [%4];"
                 : "=r"(r[0]), "=r"(r[1]), "=r"(r[2]), "=r"(r[3]) : "r"(addr));
}
__device__ __forceinline__ void ldmx2(uint32_t* r, uint32_t addr) {
    asm volatile("ldmatrix.sync.aligned.m8n8.x2.shared.b16 {%0,%1}, [%2];"
                 : "=r"(r[0]), "=r"(r[1]) : "r"(addr));
}
__device__ __forceinline__ void mma16816(float* c, const uint32_t* a,
                                         const uint32_t* b) {
    asm volatile(
        "mma.sync.aligned.m16n8k16.row.col.f32.bf16.bf16.f32 "
        "{%0,%1,%2,%3}, {%4,%5,%6,%7}, {%8,%9}, {%0,%1,%2,%3};"
        : "+f"(c[0]), "+f"(c[1]), "+f"(c[2]), "+f"(c[3])
        : "r"(a[0]), "r"(a[1]), "r"(a[2]), "r"(a[3]), "r"(b[0]), "r"(b[1]));
}

// 256-bit streaming store (Blackwell): 32 lanes x 32B = 8 full 128B lines.
__device__ __forceinline__ void stg256_cs(float* p, const float* v) {
    asm volatile(
        "st.global.cs.v8.f32 [%0], {%1,%2,%3,%4,%5,%6,%7,%8};"
        :: "l"(p), "f"(v[0]), "f"(v[1]), "f"(v[2]), "f"(v[3]),
           "f"(v[4]), "f"(v[5]), "f"(v[6]), "f"(v[7])
        : "memory");
}

// ---------------------------------------------------------------------------
// conversion kernels
// ---------------------------------------------------------------------------
__global__ void conv_x_kernel(const float* __restrict__ x) {
    int i = blockIdx.x * blockDim.x + threadIdx.x;  // float4 index
    float4 v = ((const float4*)x)[i];
    __nv_bfloat162 lo, hi;
    lo.x = __float2bfloat16(v.x); lo.y = __float2bfloat16(v.y);
    hi.x = __float2bfloat16(v.z); hi.y = __float2bfloat16(v.w);
    uint2 u;
    u.x = *(uint32_t*)&lo; u.y = *(uint32_t*)&hi;
    ((uint2*)g_xb)[i] = u;
}

// W^T with permuted rows (within aligned 32-row groups).
__global__ void conv_wt_kernel(const float* __restrict__ W) {
    __shared__ float t[32][33];
    int bx = blockIdx.x * 32, by = blockIdx.y * 32;
#pragma unroll
    for (int j = 0; j < 4; j++)
        t[threadIdx.y + j * 8][threadIdx.x] =
            W[(size_t)(by + threadIdx.y + j * 8) * EPROJ + bx + threadIdx.x];
    __syncthreads();
#pragma unroll
    for (int j = 0; j < 4; j++) {
        const int lr = threadIdx.y + j * 8;          // 0..31 within group
        g_wt[(size_t)(bx + permg(lr)) * HIDDEN + by + threadIdx.x] =
            __float2bfloat16(t[threadIdx.x][lr]);
    }
}

// ---------------------------------------------------------------------------
// Kernel 1: proj = x @ W (+bias) then RoPE -> g_q / g_k (bf16)
// (R9 config: ~94us incl. convs, ~88% of SIMT-HMMA ceiling.)
// ---------------------------------------------------------------------------
__global__ void __launch_bounds__(256, 2) proj_kernel(const float* __restrict__ bias) {
    __shared__ __align__(128) __nv_bfloat16 sA[128 * 64];
    __shared__ __align__(128) __nv_bfloat16 sB[128 * 64];
    __shared__ float s_inv[32];
    __shared__ float s_bias[128];

    const int tid = threadIdx.x;
    const int lane = tid & 31;
    const int wid = tid >> 5;
    const int wm = wid & 1;
    const int wn = wid >> 1;
    const int h = blockIdx.x;
    const int rowBase = blockIdx.y * 128;
    const int colBase = h * 128;

    if (tid < 32) s_inv[tid] = exp2f(-(float)(2 * tid) * (13.287712379549449f / 64.0f));
    if (tid < 128) s_bias[tid] = bias[colBase + tid];

    const uint32_t sAb = smem_u32(sA);
    const uint32_t sBb = smem_u32(sB);

    float acc[4][4][4] = {};

    for (int ch = 0; ch < 12; ch++) {
        const int k0 = ch * 64;
        __syncthreads();
#pragma unroll
        for (int i = 0; i < 4; i++) {
            int e = tid + i * 256;
            int r = e >> 3;
            int c = e & 7;
            uint32_t so = SWZ((uint32_t)(r * 128 + c * 16));
            *(uint4*)((char*)sA + so) =
                *(const uint4*)(g_xb + (size_t)(rowBase + r) * HIDDEN + k0 + c * 8);
            *(uint4*)((char*)sB + so) =
                *(const uint4*)(g_wt + (size_t)(colBase + r) * HIDDEN + k0 + c * 8);
        }
        __syncthreads();

#pragma unroll
        for (int ks = 0; ks < 4; ks++) {
            uint32_t aF[4][4], bF[4][2];
#pragma unroll
            for (int mi = 0; mi < 4; mi++) {
                int r = wm * 64 + mi * 16 + (lane & 15);
                int cc = ks * 2 + (lane >> 4);
                ldmx4(aF[mi], sAb + SWZ((uint32_t)(r * 128 + cc * 16)));
            }
#pragma unroll
            for (int ni = 0; ni < 4; ni++) {
                int l = lane & 15;
                int r = wn * 32 + ni * 8 + (l & 7);
                int cc = ks * 2 + (l >> 3);
                ldmx2(bF[ni], sBb + SWZ((uint32_t)(r * 128 + cc * 16)));
            }
#pragma unroll
            for (int mi = 0; mi < 4; mi++)
#pragma unroll
                for (int ni = 0; ni < 4; ni++)
                    mma16816(acc[mi][ni], aF[mi], bF[ni]);
        }
    }

    const int bc = wn * 32 + (lane & 3) * 8;
    const int half = (bc >> 6) & 1;
    const int d0 = bc & 63;
    __nv_bfloat16* dstBase = half ? g_k : g_q;
#pragma unroll
    for (int mi = 0; mi < 4; mi++) {
#pragma unroll
        for (int rr = 0; rr < 2; rr++) {
            const int r = rowBase + wm * 64 + mi * 16 + (lane >> 2) + rr * 8;
            const int bb = r >> 10;
            const int n = r & (SEQ - 1);
            const int nw = half ? ((n & ~31) | permg(n & 31)) : n;
            const float fn = (float)n;
            __nv_bfloat16* drow =
                dstBase + ((size_t)(bb * HEADS + h) * SEQ + nw) * HEAD_SIZE;
            uint32_t pk[4];
#pragma unroll
            for (int j = 0; j < 4; j++) {
                float s, cs;
                sincosf(fn * s_inv[(d0 >> 1) + j], &s, &cs);
                const float v0 = acc[mi][j][rr * 2 + 0] + s_bias[bc + 2 * j];
                const float v1 = acc[mi][j][rr * 2 + 1] + s_bias[bc + 2 * j + 1];
                __nv_bfloat162 o;
                o.x = __float2bfloat16(v0 * cs - v1 * s);
                o.y = __float2bfloat16(v1 * cs + v0 * s);
                pk[j] = *(uint32_t*)&o;
            }
            uint4 u;
            u.x = pk[0]; u.y = pk[1]; u.z = pk[2]; u.w = pk[3];
            *(uint4*)(drow + d0) = u;
        }
    }
}

// ---------------------------------------------------------------------------
// Kernel 2: logits tile 128(m) x 64(n) per CTA, 3 CTAs/SM. 8 warps: 4(m)x2(n).
// Causal skip below the diagonal. Epilogue: ONE st.global.cs.v8.f32 per
// fragment (32 lanes x 32B = 8 full 128B lines; streaming hint keeps the
// never-re-read 402MB output from thrashing L2).
// ---------------------------------------------------------------------------
__global__ void __launch_bounds__(256, 3) logits_kernel(const float* __restrict__ mask,
                                                        float* __restrict__ out) {
    __shared__ __align__(128) __nv_bfloat16 sQ[128 * 64];  // 16KB
    __shared__ __align__(128) __nv_bfloat16 sK[64 * 64];   // 8KB
    __shared__ float s_mk[64];

    const int tid = threadIdx.x;
    const int lane = tid & 31;
    const int wid = tid >> 5;
    const int wm = wid & 3;    // 0..3 (m)
    const int wn = wid >> 2;   // 0..1 (n)
    const int z = blockIdx.z;
    const int b = z / HEADS;
    const int m0 = blockIdx.y << 7;
    const int n0 = blockIdx.x << 6;

    if (tid < 64) s_mk[tid] = mask[(size_t)b * SEQ + n0 + tid];

    float acc[2][4][4] = {};

    const bool skip = (m0 >= n0 + 64);   // tile strictly below diagonal
    if (!skip) {
        const __nv_bfloat16* qsrc = g_q + ((size_t)z * SEQ + m0) * HEAD_SIZE;
        const __nv_bfloat16* ksrc = g_k + ((size_t)z * SEQ + n0) * HEAD_SIZE;

#pragma unroll
        for (int i = 0; i < 4; i++) {     // 1024 uint4 for Q
            int e = tid + i * 256;
            uint32_t so = SWZ((uint32_t)(e * 16));
            *(uint4*)((char*)sQ + so) = ((const uint4*)qsrc)[e];
        }
#pragma unroll
        for (int i = 0; i < 2; i++) {     // 512 uint4 for K
            int e = tid + i * 256;
            uint32_t so = SWZ((uint32_t)(e * 16));
            *(uint4*)((char*)sK + so) = ((const uint4*)ksrc)[e];
        }
        __syncthreads();

        const uint32_t sQb = smem_u32(sQ);
        const uint32_t sKb = smem_u32(sK);

#pragma unroll
        for (int ks = 0; ks < 4; ks++) {
            uint32_t aF[2][4], bF[4][2];
#pragma unroll
            for (int mi = 0; mi < 2; mi++) {
                int r = wm * 32 + mi * 16 + (lane & 15);
                int cc = ks * 2 + (lane >> 4);
                ldmx4(aF[mi], sQb + SWZ((uint32_t)(r * 128 + cc * 16)));
            }
#pragma unroll
            for (int ni = 0; ni < 4; ni++) {
                int l = lane & 15;
                int r = wn * 32 + ni * 8 + (l & 7);
                int cc = ks * 2 + (l >> 3);
                ldmx2(bF[ni], sKb + SWZ((uint32_t)(r * 128 + cc * 16)));
            }
#pragma unroll
            for (int mi = 0; mi < 2; mi++)
#pragma unroll
                for (int ni = 0; ni < 4; ni++)
                    mma16816(acc[mi][ni], aF[mi], bF[ni]);
        }
    } else {
        __syncthreads();
    }

    // Epilogue: lane owns cols bc..bc+7. Per-lane col factors (x0.125 folded):
    // v = (acc*mq + rbias)*s_j + o_j  (- 0.125*NEG if causal).
    const int bc = wn * 32 + (lane & 3) * 8;
    float s_j[8], o_j[8];
#pragma unroll
    for (int j = 0; j < 8; j++) {
        const float mk = s_mk[bc + j];
        s_j[j] = mk * 0.125f;
        o_j[j] = (NEGV * 0.125f) * (mk - 1.0f);
    }
#pragma unroll
    for (int mi = 0; mi < 2; mi++) {
#pragma unroll
        for (int rr = 0; rr < 2; rr++) {
            const int m = m0 + wm * 32 + mi * 16 + (lane >> 2) + rr * 8;
            const float mq = mask[(size_t)b * SEQ + m];
            const float rbias = NEGV * (mq - 1.0f);
            float* orow = out + ((size_t)z * SEQ + m) * SEQ + n0;
            float v[8];
#pragma unroll
            for (int j = 0; j < 4; j++) {
#pragma unroll
                for (int q = 0; q < 2; q++) {
                    const int jj = 2 * j + q;
                    const float t = fmaf(acc[mi][j][rr * 2 + q], mq, rbias);
                    float r = fmaf(t, s_j[jj], o_j[jj]);
                    if (m > n0 + bc + jj) r -= (NEGV * 0.125f);
                    v[jj] = r;
                }
            }
            stg256_cs(orow + bc, v);
        }
    }
}

// ---------------------------------------------------------------------------
extern "C" void kernel_launch(void* const* d_in, const int* in_sizes, int n_in,
                              void* d_out, int out_size) {
    const float* x = (const float*)d_in[0];
    const float* W = (const float*)d_in[1];
    const float* bias = (const float*)d_in[2];
    const float* mask = (const float*)d_in[3];
    float* out = (float*)d_out;

    conv_x_kernel<<<(NB * SEQ * HIDDEN / 4) / 256, 256>>>(x);
    conv_wt_kernel<<<dim3(EPROJ / 32, HIDDEN / 32), dim3(32, 8)>>>(W);

    proj_kernel<<<dim3(EPROJ / 128, NB * SEQ / 128), 256>>>(bias);

    logits_kernel<<<dim3(SEQ / 64, SEQ / 128, NB * HEADS), 256>>>(mask, out);
}

// round 13
// speedup vs baseline: 1.1870x; 1.0233x over previous
#include <cuda_runtime.h>
#include <cuda_bf16.h>
#include <stdint.h>
#include <math.h>

#define HEADS 12
#define HEAD_SIZE 64
#define HIDDEN 768
#define EPROJ 1536
#define SEQ 1024
#define NB 8
#define NEGV 1000000000000.0f

// staging buffers
__device__ __align__(128) uint8_t g_x8[NB * SEQ * HIDDEN];          // x e4m3, scale 1
__device__ __align__(128) uint8_t g_w8[EPROJ * HIDDEN];             // W^T e4m3 *64, rows permuted
__device__ __align__(128) __nv_bfloat16 g_q[NB * HEADS * SEQ * HEAD_SIZE];
__device__ __align__(128) __nv_bfloat16 g_k[NB * HEADS * SEQ * HEAD_SIZE]; // rows permuted

#define SWZ(o) ((o) ^ (((o) >> 3) & 0x70))

// Involutive permutation within 32-row groups: c = (a<<3)|(b<<1)|q -> (b<<3)|(a<<1)|q.
__device__ __forceinline__ int permg(int c) {
    return (((c & 7) >> 1) << 3) + ((c >> 3) << 1) + (c & 1);
}

__device__ __forceinline__ uint32_t smem_u32(const void* p) {
    uint32_t a;
    asm("{ .reg .u64 t; cvta.to.shared.u64 t, %1; cvt.u32.u64 %0, t; }"
        : "=r"(a) : "l"(p));
    return a;
}

__device__ __forceinline__ void ldmx4(uint32_t* r, uint32_t addr) {
    asm volatile("ldmatrix.sync.aligned.m8n8.x4.shared.b16 {%0,%1,%2,%3}, [%4];"
                 : "=r"(r[0]), "=r"(r[1]), "=r"(r[2]), "=r"(r[3]) : "r"(addr));
}
__device__ __forceinline__ void ldmx2(uint32_t* r, uint32_t addr) {
    asm volatile("ldmatrix.sync.aligned.m8n8.x2.shared.b16 {%0,%1}, [%2];"
                 : "=r"(r[0]), "=r"(r[1]) : "r"(addr));
}
__device__ __forceinline__ void mma16816(float* c, const uint32_t* a,
                                         const uint32_t* b) {
    asm volatile(
        "mma.sync.aligned.m16n8k16.row.col.f32.bf16.bf16.f32 "
        "{%0,%1,%2,%3}, {%4,%5,%6,%7}, {%8,%9}, {%0,%1,%2,%3};"
        : "+f"(c[0]), "+f"(c[1]), "+f"(c[2]), "+f"(c[3])
        : "r"(a[0]), "r"(a[1]), "r"(a[2]), "r"(a[3]), "r"(b[0]), "r"(b[1]));
}
// fp8 e4m3 mma, K=32, fp32 accum
__device__ __forceinline__ void mma8(float* c, const uint32_t* a,
                                     const uint32_t* b) {
    asm volatile(
        "mma.sync.aligned.m16n8k32.row.col.f32.e4m3.e4m3.f32 "
        "{%0,%1,%2,%3}, {%4,%5,%6,%7}, {%8,%9}, {%0,%1,%2,%3};"
        : "+f"(c[0]), "+f"(c[1]), "+f"(c[2]), "+f"(c[3])
        : "r"(a[0]), "r"(a[1]), "r"(a[2]), "r"(a[3]), "r"(b[0]), "r"(b[1]));
}

__device__ __forceinline__ uint16_t pack2_e4m3(float lo, float hi) {
    uint16_t r;
    asm("cvt.rn.satfinite.e4m3x2.f32 %0, %1, %2;" : "=h"(r) : "f"(hi), "f"(lo));
    return r;
}
__device__ __forceinline__ uint32_t pack4_e4m3(float a0, float a1, float a2,
                                               float a3) {
    uint16_t lo = pack2_e4m3(a0, a1);
    uint16_t hi = pack2_e4m3(a2, a3);
    return (uint32_t)lo | ((uint32_t)hi << 16);
}

// 256-bit streaming store (Blackwell): 32 lanes x 32B = 8 full 128B lines.
__device__ __forceinline__ void stg256_cs(float* p, const float* v) {
    asm volatile(
        "st.global.cs.v8.f32 [%0], {%1,%2,%3,%4,%5,%6,%7,%8};"
        :: "l"(p), "f"(v[0]), "f"(v[1]), "f"(v[2]), "f"(v[3]),
           "f"(v[4]), "f"(v[5]), "f"(v[6]), "f"(v[7])
        : "memory");
}

// ---------------------------------------------------------------------------
// conversion kernels
// ---------------------------------------------------------------------------
__global__ void conv_x_kernel(const float* __restrict__ x) {
    int i = blockIdx.x * blockDim.x + threadIdx.x;  // 8 floats per thread
    float4 v0 = ((const float4*)x)[i * 2];
    float4 v1 = ((const float4*)x)[i * 2 + 1];
    uint2 u;
    u.x = pack4_e4m3(v0.x, v0.y, v0.z, v0.w);
    u.y = pack4_e4m3(v1.x, v1.y, v1.z, v1.w);
    ((uint2*)g_x8)[i] = u;
}

// W^T e4m3 (*64), rows permuted within aligned 32-groups.
__global__ void conv_wt_kernel(const float* __restrict__ W) {
    __shared__ float t[32][33];
    const int bx = blockIdx.x * 32, by = blockIdx.y * 32;  // bx: e rows out, by: d cols out
    const int tx = threadIdx.x, ty = threadIdx.y;
#pragma unroll
    for (int j = 0; j < 4; j++)
        t[ty + j * 8][tx] = W[(size_t)(by + ty + j * 8) * EPROJ + bx + tx];
    __syncthreads();
    const int r2 = ty + (tx >> 3) * 8;   // out-row (e) 0..31 within group
    const int c4 = (tx & 7) * 4;         // out-col (d) group
    uint32_t p = pack4_e4m3(t[c4 + 0][r2] * 64.f, t[c4 + 1][r2] * 64.f,
                            t[c4 + 2][r2] * 64.f, t[c4 + 3][r2] * 64.f);
    *(uint32_t*)(g_w8 + (size_t)(bx + permg(r2)) * HIDDEN + by + c4) = p;
}

// ---------------------------------------------------------------------------
// Kernel 1: proj = x @ W (+bias) then RoPE -> g_q / g_k (bf16)
// FP8 e4m3 mma m16n8k32. CTA tile 128x128, K in 6 chunks of 128 (fp8 = 128B
// rows, SW128). 8 warps: 2(m) x 4(n). g_w8 pre-permuted -> linear loads +
// contiguous-col epilogue. acc scale 64 -> unscale in epilogue.
// ---------------------------------------------------------------------------
__global__ void __launch_bounds__(256, 2) proj_kernel(const float* __restrict__ bias) {
    __shared__ __align__(128) uint8_t sA[128 * 128];  // 16KB
    __shared__ __align__(128) uint8_t sB[128 * 128];  // 16KB
    __shared__ float s_inv[32];
    __shared__ float s_bias[128];

    const int tid = threadIdx.x;
    const int lane = tid & 31;
    const int wid = tid >> 5;
    const int wm = wid & 1;
    const int wn = wid >> 1;
    const int h = blockIdx.x;
    const int rowBase = blockIdx.y * 128;
    const int colBase = h * 128;

    if (tid < 32) s_inv[tid] = exp2f(-(float)(2 * tid) * (13.287712379549449f / 64.0f));
    if (tid < 128) s_bias[tid] = bias[colBase + tid];

    const uint32_t sAb = smem_u32(sA);
    const uint32_t sBb = smem_u32(sB);

    float acc[4][4][4] = {};

    for (int ch = 0; ch < 6; ch++) {
        const int k0 = ch * 128;
        __syncthreads();
#pragma unroll
        for (int i = 0; i < 4; i++) {
            int e = tid + i * 256;   // 1024 uint4 per tile
            int r = e >> 3;
            int c = e & 7;
            uint32_t so = SWZ((uint32_t)(r * 128 + c * 16));
            *(uint4*)(sA + so) =
                *(const uint4*)(g_x8 + (size_t)(rowBase + r) * HIDDEN + k0 + c * 16);
            *(uint4*)(sB + so) =
                *(const uint4*)(g_w8 + (size_t)(colBase + r) * HIDDEN + k0 + c * 16);
        }
        __syncthreads();

#pragma unroll
        for (int ks = 0; ks < 4; ks++) {   // 4 x K=32 per 128B chunk
            uint32_t aF[4][4], bF[4][2];
#pragma unroll
            for (int mi = 0; mi < 4; mi++) {
                int r = wm * 64 + mi * 16 + (lane & 15);
                int cc = ks * 2 + (lane >> 4);
                ldmx4(aF[mi], sAb + SWZ((uint32_t)(r * 128 + cc * 16)));
            }
#pragma unroll
            for (int ni = 0; ni < 4; ni++) {
                int l = lane & 15;
                int r = wn * 32 + ni * 8 + (l & 7);
                int cc = ks * 2 + (l >> 3);
                ldmx2(bF[ni], sBb + SWZ((uint32_t)(r * 128 + cc * 16)));
            }
#pragma unroll
            for (int mi = 0; mi < 4; mi++)
#pragma unroll
                for (int ni = 0; ni < 4; ni++)
                    mma8(acc[mi][ni], aF[mi], bF[ni]);
        }
    }

    // Epilogue: lane owns cols bc..bc+7; unscale 1/64, +bias, RoPE, bf16,
    // one 16B store per (mi, rr). k rows stored permuted.
    const int bc = wn * 32 + (lane & 3) * 8;
    const int half = (bc >> 6) & 1;
    const int d0 = bc & 63;
    __nv_bfloat16* dstBase = half ? g_k : g_q;
#pragma unroll
    for (int mi = 0; mi < 4; mi++) {
#pragma unroll
        for (int rr = 0; rr < 2; rr++) {
            const int r = rowBase + wm * 64 + mi * 16 + (lane >> 2) + rr * 8;
            const int bb = r >> 10;
            const int n = r & (SEQ - 1);
            const int nw = half ? ((n & ~31) | permg(n & 31)) : n;
            const float fn = (float)n;
            __nv_bfloat16* drow =
                dstBase + ((size_t)(bb * HEADS + h) * SEQ + nw) * HEAD_SIZE;
            uint32_t pk[4];
#pragma unroll
            for (int j = 0; j < 4; j++) {
                float s, cs;
                sincosf(fn * s_inv[(d0 >> 1) + j], &s, &cs);
                const float v0 = acc[mi][j][rr * 2 + 0] * 0.015625f + s_bias[bc + 2 * j];
                const float v1 = acc[mi][j][rr * 2 + 1] * 0.015625f + s_bias[bc + 2 * j + 1];
                __nv_bfloat162 o;
                o.x = __float2bfloat16(v0 * cs - v1 * s);
                o.y = __float2bfloat16(v1 * cs + v0 * s);
                pk[j] = *(uint32_t*)&o;
            }
            uint4 u;
            u.x = pk[0]; u.y = pk[1]; u.z = pk[2]; u.w = pk[3];
            *(uint4*)(drow + d0) = u;
        }
    }
}

// ---------------------------------------------------------------------------
// Kernel 2: logits tile 128(m) x 64(n) per CTA, 3 CTAs/SM (unchanged R12).
// ---------------------------------------------------------------------------
__global__ void __launch_bounds__(256, 3) logits_kernel(const float* __restrict__ mask,
                                                        float* __restrict__ out) {
    __shared__ __align__(128) __nv_bfloat16 sQ[128 * 64];  // 16KB
    __shared__ __align__(128) __nv_bfloat16 sK[64 * 64];   // 8KB
    __shared__ float s_mk[64];

    const int tid = threadIdx.x;
    const int lane = tid & 31;
    const int wid = tid >> 5;
    const int wm = wid & 3;    // 0..3 (m)
    const int wn = wid >> 2;   // 0..1 (n)
    const int z = blockIdx.z;
    const int b = z / HEADS;
    const int m0 = blockIdx.y << 7;
    const int n0 = blockIdx.x << 6;

    if (tid < 64) s_mk[tid] = mask[(size_t)b * SEQ + n0 + tid];

    float acc[2][4][4] = {};

    const bool skip = (m0 >= n0 + 64);   // tile strictly below diagonal
    if (!skip) {
        const __nv_bfloat16* qsrc = g_q + ((size_t)z * SEQ + m0) * HEAD_SIZE;
        const __nv_bfloat16* ksrc = g_k + ((size_t)z * SEQ + n0) * HEAD_SIZE;

#pragma unroll
        for (int i = 0; i < 4; i++) {     // 1024 uint4 for Q
            int e = tid + i * 256;
            uint32_t so = SWZ((uint32_t)(e * 16));
            *(uint4*)((char*)sQ + so) = ((const uint4*)qsrc)[e];
        }
#pragma unroll
        for (int i = 0; i < 2; i++) {     // 512 uint4 for K
            int e = tid + i * 256;
            uint32_t so = SWZ((uint32_t)(e * 16));
            *(uint4*)((char*)sK + so) = ((const uint4*)ksrc)[e];
        }
        __syncthreads();

        const uint32_t sQb = smem_u32(sQ);
        const uint32_t sKb = smem_u32(sK);

#pragma unroll
        for (int ks = 0; ks < 4; ks++) {
            uint32_t aF[2][4], bF[4][2];
#pragma unroll
            for (int mi = 0; mi < 2; mi++) {
                int r = wm * 32 + mi * 16 + (lane & 15);
                int cc = ks * 2 + (lane >> 4);
                ldmx4(aF[mi], sQb + SWZ((uint32_t)(r * 128 + cc * 16)));
            }
#pragma unroll
            for (int ni = 0; ni < 4; ni++) {
                int l = lane & 15;
                int r = wn * 32 + ni * 8 + (l & 7);
                int cc = ks * 2 + (l >> 3);
                ldmx2(bF[ni], sKb + SWZ((uint32_t)(r * 128 + cc * 16)));
            }
#pragma unroll
            for (int mi = 0; mi < 2; mi++)
#pragma unroll
                for (int ni = 0; ni < 4; ni++)
                    mma16816(acc[mi][ni], aF[mi], bF[ni]);
        }
    } else {
        __syncthreads();
    }

    // Epilogue: lane owns cols bc..bc+7; folded mask/causal/scale; STG.256.cs.
    const int bc = wn * 32 + (lane & 3) * 8;
    float s_j[8], o_j[8];
#pragma unroll
    for (int j = 0; j < 8; j++) {
        const float mk = s_mk[bc + j];
        s_j[j] = mk * 0.125f;
        o_j[j] = (NEGV * 0.125f) * (mk - 1.0f);
    }
#pragma unroll
    for (int mi = 0; mi < 2; mi++) {
#pragma unroll
        for (int rr = 0; rr < 2; rr++) {
            const int m = m0 + wm * 32 + mi * 16 + (lane >> 2) + rr * 8;
            const float mq = mask[(size_t)b * SEQ + m];
            const float rbias = NEGV * (mq - 1.0f);
            float* orow = out + ((size_t)z * SEQ + m) * SEQ + n0;
            float v[8];
#pragma unroll
            for (int j = 0; j < 4; j++) {
#pragma unroll
                for (int q = 0; q < 2; q++) {
                    const int jj = 2 * j + q;
                    const float t = fmaf(acc[mi][j][rr * 2 + q], mq, rbias);
                    float r = fmaf(t, s_j[jj], o_j[jj]);
                    if (m > n0 + bc + jj) r -= (NEGV * 0.125f);
                    v[jj] = r;
                }
            }
            stg256_cs(orow + bc, v);
        }
    }
}

// ---------------------------------------------------------------------------
extern "C" void kernel_launch(void* const* d_in, const int* in_sizes, int n_in,
                              void* d_out, int out_size) {
    const float* x = (const float*)d_in[0];
    const float* W = (const float*)d_in[1];
    const float* bias = (const float*)d_in[2];
    const float* mask = (const float*)d_in[3];
    float* out = (float*)d_out;

    conv_x_kernel<<<(NB * SEQ * HIDDEN / 8) / 256, 256>>>(x);
    conv_wt_kernel<<<dim3(EPROJ / 32, HIDDEN / 32), dim3(32, 8)>>>(W);

    proj_kernel<<<dim3(EPROJ / 128, NB * SEQ / 128), 256>>>(bias);

    logits_kernel<<<dim3(SEQ / 64, SEQ / 128, NB * HEADS), 256>>>(mask, out);
}